// round 1
// baseline (speedup 1.0000x reference)
#include <cuda_runtime.h>
#include <math_constants.h>

// Fixed problem shape: x[B=4, C=256, H=200, W=320] float32 -> out[B, H, W] float32
#define Bn 4
#define Cn 256
#define Hn 200
#define Wn 320
#define HWn (Hn * Wn)            // 64000
#define CHWn (Cn * HWn)          // 16384000

#define NEG_INF (-CUDART_INF_F)

// Max over the 9x9 window (clipped at borders) of one channel plane.
// Rows are 16B-aligned (W*4 = 1280B, channel stride 256000B both 16B multiples),
// so we read 3 aligned float4 per row covering [wa, wa+12) which always contains
// the valid column range [max(w-4,0), min(w+4,W-1)], and mask invalid columns.
__device__ __forceinline__ float window_max(const float* __restrict__ chan,
                                            int h, int w) {
    const int r0 = max(h - 4, 0);
    const int r1 = min(h + 4, Hn - 1);
    const int lo = w - 4;           // may be negative; cols are >= 0 anyway
    const int hi = w + 4;           // may be >= W;    cols are <= W-1 anyway
    int wa = (w - 4) & ~3;
    if (wa < 0) wa = 0;
    if (wa > Wn - 12) wa = Wn - 12; // Wn-12 = 308, multiple of 4 -> stays aligned

    float nb = NEG_INF;
    for (int r = r0; r <= r1; ++r) {
        const float4* p = reinterpret_cast<const float4*>(chan + r * Wn + wa);
        float4 a = p[0];
        float4 b = p[1];
        float4 c = p[2];
        float v[12] = {a.x, a.y, a.z, a.w, b.x, b.y, b.z, b.w, c.x, c.y, c.z, c.w};
#pragma unroll
        for (int j = 0; j < 12; ++j) {
            const int col = wa + j;
            const bool ok = (col >= lo) && (col <= hi);
            nb = fmaxf(nb, ok ? v[j] : NEG_INF);
        }
    }
    return nb;
}

__global__ void __launch_bounds__(Wn)
hard_detection_kernel(const float* __restrict__ x, float* __restrict__ out) {
    const int w = threadIdx.x;   // 0..319
    const int h = blockIdx.x;    // 0..199
    const int b = blockIdx.y;    // 0..3

    const float* __restrict__ xb = x + (size_t)b * CHWn;     // batch base
    const float* __restrict__ xp = xb + h * Wn + w;          // channel-0 element

    // ---- Phase A: depth-wise max / argmax / tie-count, 4 independent lanes ----
    float m0 = NEG_INF, m1 = NEG_INF, m2 = NEG_INF, m3 = NEG_INF;
    int   a0 = 0, a1 = 0, a2 = 0, a3 = 0;
    int   n0 = 0, n1 = 0, n2 = 0, n3 = 0;

#pragma unroll 4
    for (int c = 0; c < Cn; c += 4) {
        const float v0 = xp[(size_t)(c + 0) * HWn];
        const float v1 = xp[(size_t)(c + 1) * HWn];
        const float v2 = xp[(size_t)(c + 2) * HWn];
        const float v3 = xp[(size_t)(c + 3) * HWn];
        if (v0 > m0)       { m0 = v0; a0 = c + 0; n0 = 1; }
        else if (v0 == m0) { n0++; }
        if (v1 > m1)       { m1 = v1; a1 = c + 1; n1 = 1; }
        else if (v1 == m1) { n1++; }
        if (v2 > m2)       { m2 = v2; a2 = c + 2; n2 = 1; }
        else if (v2 == m2) { n2++; }
        if (v3 > m3)       { m3 = v3; a3 = c + 3; n3 = 1; }
        else if (v3 == m3) { n3++; }
    }

    // Merge the 4 accumulators (cstar is only meaningful when total count == 1).
    if (m1 > m0)       { m0 = m1; a0 = a1; n0 = n1; }
    else if (m1 == m0) { n0 += n1; }
    if (m2 > m0)       { m0 = m2; a0 = a2; n0 = n2; }
    else if (m2 == m0) { n0 += n2; }
    if (m3 > m0)       { m0 = m3; a0 = a3; n0 = n3; }
    else if (m3 == m0) { n0 += n3; }

    // ---- Phase B: 9x9 local-max test on the argmax channel only ----
    float res;
    if (n0 == 1) {
        const float* chan = xb + (size_t)a0 * HWn;
        const float nb = window_max(chan, h, w);
        res = (nb <= m0) ? m0 : 0.0f;   // nb >= m0 always (center included)
    } else {
        // Exact tie path (expected ~0 pixels): every channel equal to the max
        // contributes m0 if it is also its own 9x9 local max.
        int k = 0;
        for (int c = 0; c < Cn; ++c) {
            const float v = xp[(size_t)c * HWn];
            if (v == m0) {
                const float* chan = xb + (size_t)c * HWn;
                if (window_max(chan, h, w) <= m0) k++;
            }
        }
        res = m0 * (float)k;
    }

    out[(b * Hn + h) * Wn + w] = res;
}

extern "C" void kernel_launch(void* const* d_in, const int* in_sizes, int n_in,
                              void* d_out, int out_size) {
    const float* x = (const float*)d_in[0];
    float* out = (float*)d_out;
    (void)in_sizes; (void)n_in; (void)out_size;

    dim3 grid(Hn, Bn);   // (200, 4) blocks, one block per output row
    dim3 block(Wn);      // 320 threads, one per output column
    hard_detection_kernel<<<grid, block>>>(x, out);
}